// round 7
// baseline (speedup 1.0000x reference)
#include <cuda_runtime.h>
#include <cuda_bf16.h>

// Problem dims
#define BB    8
#define TOUT  256
#define TIN   512
#define LL    128
#define DIN   128
#define DATT  128
#define GG    512   // 4*L

// Scratch (device globals: no allocation allowed)
__device__ float g_keys[BB * TIN * LL];    // 2 MB
__device__ float g_xz[BB * TOUT * GG];     // 4 MB

__device__ __forceinline__ float fast_tanh(float x) {
    float y;
    asm("tanh.approx.f32 %0, %1;" : "=f"(y) : "f"(x));
    return y;
}
__device__ __forceinline__ float sigm_acc(float x) {
    return 1.0f / (1.0f + __expf(-x));
}
__device__ __forceinline__ float tanh_acc(float x) {
    return 2.0f / (1.0f + __expf(-2.0f * x)) - 1.0f;
}
// packed f32x2 fma (sm_103a): d = a*b + c lanewise on 2 floats in a u64
__device__ __forceinline__ unsigned long long ffma2(unsigned long long a,
                                                    unsigned long long b,
                                                    unsigned long long c) {
    unsigned long long d;
    asm("fma.rn.f32x2 %0, %1, %2, %3;" : "=l"(d) : "l"(a), "l"(b), "l"(c));
    return d;
}
__device__ __forceinline__ unsigned long long pack2(float lo, float hi) {
    unsigned long long p;
    asm("mov.b64 %0, {%1, %2};" : "=l"(p) : "f"(lo), "f"(hi));
    return p;
}
__device__ __forceinline__ float2 unpack2(unsigned long long p) {
    float lo, hi;
    asm("mov.b64 {%0, %1}, %2;" : "=f"(lo), "=f"(hi) : "l"(p));
    return make_float2(lo, hi);
}

// ---------------------------------------------------------------------------
// Kernel 1: xz = inputs @ Wk + bias   (2048 rows x 512 cols, K=128)
// ---------------------------------------------------------------------------
__global__ void xz_kernel(const float* __restrict__ inp,
                          const float* __restrict__ Wk,
                          const float* __restrict__ bias) {
    __shared__ float a_s[16][128];
    const int tid = threadIdx.x;
    const int row0 = blockIdx.x * 16;

    const float4* src = (const float4*)(inp + row0 * DIN);
    ((float4*)&a_s[0][0])[tid] = src[tid];
    __syncthreads();

    float acc[16];
    float bj = bias[tid];
#pragma unroll
    for (int r = 0; r < 16; r++) acc[r] = bj;

    for (int d = 0; d < 128; d += 4) {
        float w0 = Wk[(d + 0) * GG + tid];
        float w1 = Wk[(d + 1) * GG + tid];
        float w2 = Wk[(d + 2) * GG + tid];
        float w3 = Wk[(d + 3) * GG + tid];
#pragma unroll
        for (int r = 0; r < 16; r++) {
            float4 a = *(const float4*)&a_s[r][d];
            acc[r] += a.x * w0 + a.y * w1 + a.z * w2 + a.w * w3;
        }
    }
#pragma unroll
    for (int r = 0; r < 16; r++)
        g_xz[(row0 + r) * GG + tid] = acc[r];
}

// ---------------------------------------------------------------------------
// Kernel 2: keys = attended @ W1 + b1  (4096 rows x 128 cols, K=128)
// ---------------------------------------------------------------------------
__global__ void keys_kernel(const float* __restrict__ att,
                            const float* __restrict__ W1,
                            const float* __restrict__ b1) {
    __shared__ float a_s[16][128];
    const int tid = threadIdx.x;
    const int row0 = blockIdx.x * 16;

    const float4* src = (const float4*)(att + row0 * DATT);
    float4* dst = (float4*)&a_s[0][0];
    for (int i = tid; i < 512; i += 128) dst[i] = src[i];
    __syncthreads();

    float acc[16];
    float bj = b1[tid];
#pragma unroll
    for (int r = 0; r < 16; r++) acc[r] = bj;

    for (int d = 0; d < 128; d += 4) {
        float w0 = W1[(d + 0) * LL + tid];
        float w1 = W1[(d + 1) * LL + tid];
        float w2 = W1[(d + 2) * LL + tid];
        float w3 = W1[(d + 3) * LL + tid];
#pragma unroll
        for (int r = 0; r < 16; r++) {
            float4 a = *(const float4*)&a_s[r][d];
            acc[r] += a.x * w0 + a.y * w1 + a.z * w2 + a.w * w3;
        }
    }
#pragma unroll
    for (int r = 0; r < 16; r++)
        g_keys[(row0 + r) * LL + tid] = acc[r];
}

// ---------------------------------------------------------------------------
// Kernel 3: LSTM scan v3 — transposed work assignment + split-K.
// grid 8 (one CTA per batch), block 512.
// Thread (l = tid>>2, k = tid&3): computes partial dot of ALL 4 gates of
// unit l over h rows [32k, 32k+32). Two shfl_xor reduce over k; lane k==0
// owns c/h for unit l in registers -> one barrier per step, no tail stage.
// Weights: 11 pairs/gate in registers (88 regs), 5 pairs/gate in smem
//   (u64, per-thread stride 46 floats -> conflict-free LDS.64).
// h: 4 skewed replicas (offset 164k floats -> each LDS.128 = 1 wavefront),
//   double-buffered across steps.
// ---------------------------------------------------------------------------
#define WST 46                                   // per-thread smem stride (floats)
#define HB_OFF (512 * WST)                       // h buffers base (floats)
#define LSTM_SMEM ((512 * WST + 2 * 528) * 4)    // 98,432 B

__global__ void __launch_bounds__(512, 1)
lstm_kernel(const float* __restrict__ Wr, float* __restrict__ out) {
    extern __shared__ float sm[];
    float* hb = sm + HB_OFF;                 // 2 bufs x 4 replicas x 132 floats

    const int tid = threadIdx.x;
    const int l   = tid >> 2;                // unit 0..127
    const int k   = tid & 3;                 // split-K 0..3
    const int b   = blockIdx.x;
    const int rb  = k * 32;                  // first h row handled

    // register weight pairs: gate g, pairs p=0..10 (rows rb+2p, rb+2p+1)
    unsigned long long wr0[11], wr1[11], wr2[11], wr3[11];
#pragma unroll
    for (int p = 0; p < 11; p++) {
        wr0[p] = pack2(Wr[(rb + 2 * p) * GG + l      ], Wr[(rb + 2 * p + 1) * GG + l      ]);
        wr1[p] = pack2(Wr[(rb + 2 * p) * GG + l + 128], Wr[(rb + 2 * p + 1) * GG + l + 128]);
        wr2[p] = pack2(Wr[(rb + 2 * p) * GG + l + 256], Wr[(rb + 2 * p + 1) * GG + l + 256]);
        wr3[p] = pack2(Wr[(rb + 2 * p) * GG + l + 384], Wr[(rb + 2 * p + 1) * GG + l + 384]);
    }
    // smem weight pairs: gate g pairs p=11..15 at u64 index g*5 + (p-11)
    unsigned long long* wst = (unsigned long long*)(sm + tid * WST);
#pragma unroll
    for (int p = 11; p < 16; p++) {
        wst[0 * 5 + p - 11]  = pack2(Wr[(rb + 2 * p) * GG + l      ], Wr[(rb + 2 * p + 1) * GG + l      ]);
        wst[1 * 5 + p - 11]  = pack2(Wr[(rb + 2 * p) * GG + l + 128], Wr[(rb + 2 * p + 1) * GG + l + 128]);
        wst[2 * 5 + p - 11]  = pack2(Wr[(rb + 2 * p) * GG + l + 256], Wr[(rb + 2 * p + 1) * GG + l + 256]);
        wst[3 * 5 + p - 11]  = pack2(Wr[(rb + 2 * p) * GG + l + 384], Wr[(rb + 2 * p + 1) * GG + l + 384]);
    }

    // zero both h buffers
    for (int i = tid; i < 2 * 528; i += 512) hb[i] = 0.0f;
    float c = 0.0f;
    __syncthreads();

    const float* xzb = g_xz + b * TOUT * GG;
    float* outx = out + b * TOUT * 256;

    // prefetch xz for t=0 (used only by k==0 lanes, loaded by all)
    float x0 = xzb[l], x1 = xzb[l + 128], x2 = xzb[l + 256], x3 = xzb[l + 384];

    for (int t = 0; t < TOUT; t++) {
        const int cur = t & 1;
        const ulonglong2* hcur = (const ulonglong2*)(hb + cur * 528 + k * 164);

        unsigned long long a0 = 0ULL, a1 = 0ULL, a2 = 0ULL, a3 = 0ULL;

#pragma unroll
        for (int j = 0; j < 8; j++) {
            ulonglong2 hv = hcur[j];
            const int pa = 2 * j, pb = 2 * j + 1;
            a0 = ffma2(pa < 11 ? wr0[pa] : wst[pa - 11],      hv.x, a0);
            a0 = ffma2(pb < 11 ? wr0[pb] : wst[pb - 11],      hv.y, a0);
            a1 = ffma2(pa < 11 ? wr1[pa] : wst[5 + pa - 11],  hv.x, a1);
            a1 = ffma2(pb < 11 ? wr1[pb] : wst[5 + pb - 11],  hv.y, a1);
            a2 = ffma2(pa < 11 ? wr2[pa] : wst[10 + pa - 11], hv.x, a2);
            a2 = ffma2(pb < 11 ? wr2[pb] : wst[10 + pb - 11], hv.y, a2);
            a3 = ffma2(pa < 11 ? wr3[pa] : wst[15 + pa - 11], hv.x, a3);
            a3 = ffma2(pb < 11 ? wr3[pb] : wst[15 + pb - 11], hv.y, a3);
        }

        float2 f0 = unpack2(a0), f1 = unpack2(a1), f2 = unpack2(a2), f3 = unpack2(a3);
        float z0 = f0.x + f0.y, z1 = f1.x + f1.y, z2 = f2.x + f2.y, z3 = f3.x + f3.y;

        // reduce over k (groups of 4 consecutive lanes)
        z0 += __shfl_xor_sync(0xffffffffu, z0, 1);
        z1 += __shfl_xor_sync(0xffffffffu, z1, 1);
        z2 += __shfl_xor_sync(0xffffffffu, z2, 1);
        z3 += __shfl_xor_sync(0xffffffffu, z3, 1);
        z0 += __shfl_xor_sync(0xffffffffu, z0, 2);
        z1 += __shfl_xor_sync(0xffffffffu, z1, 2);
        z2 += __shfl_xor_sync(0xffffffffu, z2, 2);
        z3 += __shfl_xor_sync(0xffffffffu, z3, 2);

        if (k == 0) {
            float ai = sigm_acc(z0 + x0);
            float af = sigm_acc(z1 + x1);
            float ag = tanh_acc(z2 + x2);
            float ao = sigm_acc(z3 + x3);
            c = af * c + ai * ag;
            float h = ao * tanh_acc(c);
            float* hn = hb + (cur ^ 1) * 528;
            hn[l] = h; hn[132 + l] = h; hn[264 + l] = h; hn[396 + l] = h;
            outx[t * 256 + l] = h;
        }
        if (t + 1 < TOUT) {
            const float* xn = xzb + (t + 1) * GG;
            x0 = xn[l]; x1 = xn[l + 128]; x2 = xn[l + 256]; x3 = xn[l + 384];
        }
        __syncthreads();
    }

    if (k == 0) {
        // after t=255 (cur=1), final h lives in buffer 0
        float hT = hb[l];
        out[BB * TOUT * 256 + b * LL + l]           = hT;   // h_T
        out[BB * TOUT * 256 + BB * LL + b * LL + l] = c;    // c_T
    }
}

// ---------------------------------------------------------------------------
// Kernel 4: fused q = x@W2+b2, Bahdanau scores, online softmax, weighted sum.
// (unchanged from best passing version)
// ---------------------------------------------------------------------------
#define ATTN_SMEM ((128 * 132 * 2 + 16 * 128 + 16 * 128 + 128) * 4)

__global__ void __launch_bounds__(256, 1)
attn_kernel(const float* __restrict__ attg,
            const float* __restrict__ W2,
            const float* __restrict__ b2,
            const float* __restrict__ W3,
            float* __restrict__ out) {
    extern __shared__ float sm[];
    float* keys_s = sm;                     // 128*132
    float* att_s  = sm + 128 * 132;         // 128*132
    float* q_s    = sm + 2 * 128 * 132;     // 16*128
    float* p_s    = q_s + 16 * 128;         // 16*128
    float* w3_s   = p_s + 16 * 128;         // 128

    const int tid = threadIdx.x;
    const int lane = tid & 31;
    const int wid = tid >> 5;
    const int b = blockIdx.y;
    const int t0 = blockIdx.x * 16;

    if (tid < 128) w3_s[tid] = W3[tid];
    for (int i = tid; i < 128 * 128; i += 256) {
        int d = i >> 7, cc = i & 127;
        keys_s[d * 132 + cc] = W2[i];
    }
    for (int i = tid; i < 16 * 128; i += 256) {
        int tq = i >> 7, dd = i & 127;
        att_s[tq * 132 + dd] = out[b * (TOUT * 256) + (t0 + tq) * 256 + dd];  // x
    }
    __syncthreads();

#pragma unroll
    for (int r = 0; r < 8; r++) {
        int i = r * 256 + tid;
        int tq = i >> 7, cc = i & 127;
        float acc = b2[cc];
        const float* xr = att_s + tq * 132;
#pragma unroll 8
        for (int d = 0; d < 128; d++)
            acc += xr[d] * keys_s[d * 132 + cc];
        q_s[tq * 128 + cc] = acc;
    }

    const int r0 = 2 * wid, r1 = 2 * wid + 1;
    float m0 = -1e30f, m1 = -1e30f;
    float den0 = 0.0f, den1 = 0.0f;
    float4 acc0 = make_float4(0.f, 0.f, 0.f, 0.f);
    float4 acc1 = make_float4(0.f, 0.f, 0.f, 0.f);

    const float4* q0 = (const float4*)(q_s + r0 * 128);
    const float4* q1 = (const float4*)(q_s + r1 * 128);
    const float4* w34 = (const float4*)w3_s;

    for (int kc = 0; kc < 4; kc++) {
        __syncthreads();
        const float4* ksrc = (const float4*)(g_keys + b * TIN * LL + kc * 128 * LL);
        const float4* asrc = (const float4*)(attg + b * TIN * DATT + kc * 128 * DATT);
        for (int i = tid; i < 4096; i += 256) {
            int r = i >> 5, c4 = i & 31;
            *(float4*)&keys_s[r * 132 + c4 * 4] = ksrc[i];
            *(float4*)&att_s[r * 132 + c4 * 4] = asrc[i];
        }
        __syncthreads();

        float p0[4] = {0.f, 0.f, 0.f, 0.f};
        float p1[4] = {0.f, 0.f, 0.f, 0.f};
#pragma unroll 4
        for (int l4 = 0; l4 < 32; l4++) {
            float4 wv  = w34[l4];
            float4 qv0 = q0[l4];
            float4 qv1 = q1[l4];
#pragma unroll
            for (int ks = 0; ks < 4; ks++) {
                float4 kv = *(const float4*)(keys_s + (ks * 32 + lane) * 132 + l4 * 4);
                p0[ks] += fast_tanh(kv.x + qv0.x) * wv.x + fast_tanh(kv.y + qv0.y) * wv.y
                        + fast_tanh(kv.z + qv0.z) * wv.z + fast_tanh(kv.w + qv0.w) * wv.w;
                p1[ks] += fast_tanh(kv.x + qv1.x) * wv.x + fast_tanh(kv.y + qv1.y) * wv.y
                        + fast_tanh(kv.z + qv1.z) * wv.z + fast_tanh(kv.w + qv1.w) * wv.w;
            }
        }

        float s0 = fmaxf(fmaxf(p0[0], p0[1]), fmaxf(p0[2], p0[3]));
        float s1 = fmaxf(fmaxf(p1[0], p1[1]), fmaxf(p1[2], p1[3]));
#pragma unroll
        for (int off = 16; off > 0; off >>= 1) {
            s0 = fmaxf(s0, __shfl_xor_sync(0xffffffffu, s0, off));
            s1 = fmaxf(s1, __shfl_xor_sync(0xffffffffu, s1, off));
        }
        float mn0 = fmaxf(m0, s0), mn1 = fmaxf(m1, s1);
        float sc0 = __expf(m0 - mn0), sc1 = __expf(m1 - mn1);
        den0 *= sc0; den1 *= sc1;
        acc0.x *= sc0; acc0.y *= sc0; acc0.z *= sc0; acc0.w *= sc0;
        acc1.x *= sc1; acc1.y *= sc1; acc1.z *= sc1; acc1.w *= sc1;
        m0 = mn0; m1 = mn1;

#pragma unroll
        for (int ks = 0; ks < 4; ks++) {
            float e0 = __expf(p0[ks] - mn0);
            float e1 = __expf(p1[ks] - mn1);
            den0 += e0; den1 += e1;
            p_s[r0 * 128 + ks * 32 + lane] = e0;
            p_s[r1 * 128 + ks * 32 + lane] = e1;
        }
        __syncwarp();

        const float* pr0 = p_s + r0 * 128;
        const float* pr1 = p_s + r1 * 128;
#pragma unroll 2
        for (int kk = 0; kk < 128; kk++) {
            float pv0 = pr0[kk];
            float pv1 = pr1[kk];
            float4 av = *(const float4*)(att_s + kk * 132 + lane * 4);
            acc0.x += pv0 * av.x; acc0.y += pv0 * av.y;
            acc0.z += pv0 * av.z; acc0.w += pv0 * av.w;
            acc1.x += pv1 * av.x; acc1.y += pv1 * av.y;
            acc1.z += pv1 * av.z; acc1.w += pv1 * av.w;
        }
    }

#pragma unroll
    for (int off = 16; off > 0; off >>= 1) {
        den0 += __shfl_xor_sync(0xffffffffu, den0, off);
        den1 += __shfl_xor_sync(0xffffffffu, den1, off);
    }
    float inv0 = 1.0f / den0, inv1 = 1.0f / den1;

    float* od0 = out + b * (TOUT * 256) + (t0 + r0) * 256 + 128;
    float* od1 = out + b * (TOUT * 256) + (t0 + r1) * 256 + 128;
    *(float4*)(od0 + lane * 4) = make_float4(acc0.x * inv0, acc0.y * inv0,
                                             acc0.z * inv0, acc0.w * inv0);
    *(float4*)(od1 + lane * 4) = make_float4(acc1.x * inv1, acc1.y * inv1,
                                             acc1.z * inv1, acc1.w * inv1);
}

// ---------------------------------------------------------------------------
extern "C" void kernel_launch(void* const* d_in, const int* in_sizes, int n_in,
                              void* d_out, int out_size) {
    const float* inputs   = (const float*)d_in[0];
    const float* attended = (const float*)d_in[1];
    const float* Wk       = (const float*)d_in[2];
    const float* Wr       = (const float*)d_in[3];
    const float* bias     = (const float*)d_in[4];
    const float* W1       = (const float*)d_in[5];
    const float* b1       = (const float*)d_in[6];
    const float* W2       = (const float*)d_in[7];
    const float* b2       = (const float*)d_in[8];
    const float* W3       = (const float*)d_in[9];
    // d_in[10] = b3: constant shift of scores -> softmax-invariant, unused.
    float* out = (float*)d_out;

    cudaFuncSetAttribute(lstm_kernel, cudaFuncAttributeMaxDynamicSharedMemorySize, LSTM_SMEM);
    cudaFuncSetAttribute(attn_kernel, cudaFuncAttributeMaxDynamicSharedMemorySize, ATTN_SMEM);

    xz_kernel<<<128, 512>>>(inputs, Wk, bias);
    keys_kernel<<<256, 128>>>(attended, W1, b1);
    lstm_kernel<<<8, 512, LSTM_SMEM>>>(Wr, out);
    attn_kernel<<<dim3(16, 8), 256, ATTN_SMEM>>>(attended, W2, b2, W3, out);
}